// round 11
// baseline (speedup 1.0000x reference)
#include <cuda_runtime.h>

#define BN 64
#define TN 512
#define LN 48
#define CL 32            // chunk length (steps)
#define NC 16            // chunks per batch = TN/CL
#define START_I 46
#define PAD_I 45
#define END_I 47

__device__ float g_dir[BN][NC][LN];   // forward chunk output directions (L1-normalized)
__device__ float g_a[BN][NC][LN];     // backward chunk left directions (c>=1, L1-normalized)
__device__ float g_S[BN][NC];         // forward log-magnitudes from ones
__device__ float g_tg[BN];
__device__ float g_val[BN];
__device__ unsigned g_bd[BN];         // per-batch arrival counters (self-reset)
__device__ unsigned g_done;           // global arrival counter (self-reset)

#define FMA_F32X2(d, a, b, c) \
    asm("fma.rn.f32x2 %0, %1, %2, %3;" : "=l"(d) : "l"(a), "l"(b), "l"(c))
#define ADD_F32X2_(d, a, b) \
    asm("add.rn.f32x2 %0, %1, %2;" : "=l"(d) : "l"(a), "l"(b))
#define PACK_F32X2_(d, lo, hi) \
    asm("mov.b64 %0, {%1, %2};" : "=l"(d) : "f"(lo), "f"(hi))
#define UNPACK_F32X2_(lo, hi, s) \
    asm("mov.b64 {%0, %1}, %2;" : "=f"(lo), "=f"(hi) : "l"(s))

// packed dual dot-product over the 48-vector in sh (12 LDS.128 + 48 FFMA2)
#define DUAL_DOT(shp, Ex, Ey, out0, out1)                                   \
    {                                                                        \
        const ulonglong2* w2_ = (const ulonglong2*)(shp);                    \
        unsigned long long a0=0ull,a1=0ull,a2=0ull,a3=0ull;                  \
        unsigned long long b0=0ull,b1=0ull,b2=0ull,b3=0ull;                  \
        _Pragma("unroll")                                                    \
        for (int q = 0; q < LN / 4; q++) {                                   \
            const ulonglong2 wq = w2_[q];                                    \
            if ((q & 1) == 0) {                                              \
                FMA_F32X2(a0, wq.x, (Ex)[2*q],   a0);                        \
                FMA_F32X2(a1, wq.y, (Ex)[2*q+1], a1);                        \
                FMA_F32X2(b0, wq.x, (Ey)[2*q],   b0);                        \
                FMA_F32X2(b1, wq.y, (Ey)[2*q+1], b1);                        \
            } else {                                                         \
                FMA_F32X2(a2, wq.x, (Ex)[2*q],   a2);                        \
                FMA_F32X2(a3, wq.y, (Ex)[2*q+1], a3);                        \
                FMA_F32X2(b2, wq.x, (Ey)[2*q],   b2);                        \
                FMA_F32X2(b3, wq.y, (Ey)[2*q+1], b3);                        \
            }                                                                \
        }                                                                    \
        unsigned long long sA_, sB_, x_, y_;                                 \
        ADD_F32X2_(x_, a0, a1); ADD_F32X2_(y_, a2, a3); ADD_F32X2_(sA_, x_, y_); \
        ADD_F32X2_(x_, b0, b1); ADD_F32X2_(y_, b2, b3); ADD_F32X2_(sB_, x_, y_); \
        float lo_, hi_;                                                      \
        UNPACK_F32X2_(lo_, hi_, sA_); (out0) = lo_ + hi_;                    \
        UNPACK_F32X2_(lo_, hi_, sB_); (out1) = lo_ + hi_;                    \
    }

// ---- forward CL-step scan (validated round-10 loop) ----
// Lane t < 24 owns columns (2t, 2t+1); u in scaled linear domain.
__device__ __forceinline__ void chunk_scan_fw(
    const float* __restrict__ scp, const int* __restrict__ mp,
    const unsigned long long* Ea, const unsigned long long* Eb,
    float& u0, float& u1, bool act, int lane,
    float sh_w[2][LN], int sh_k[2], int* K_out)
{
    int K = 0, kcur = 0;
    if (lane == 0) { sh_k[0] = 0; sh_k[1] = 0; }

    float es0[4], es1[4];
    int mb[4];
#pragma unroll
    for (int q = 0; q < 4; q++) {
        const float2 sv = *(const float2*)(scp + q * LN);
        es0[q] = __expf(sv.x);
        es1[q] = __expf(sv.y);
        mb[q] = mp[q];
    }

    float w0 = u0 * es0[0], w1 = u1 * es1[0];
    __syncwarp();

    for (int t0 = 0; t0 < CL; t0 += 4) {
#pragma unroll
        for (int k = 0; k < 4; k++) {
            const int t = t0 + k;
            const int p = t & 1;
            const int msk = mb[k];

            if (act) {
                unsigned long long wp;
                PACK_F32X2_(wp, w0, w1);
                *(unsigned long long*)&sh_w[p][2 * lane] = wp;
            }
            __syncwarp();

            const int knext = sh_k[p ^ 1];
            const float scn = __int_as_float((127 - knext) << 23);
            K += kcur;
            const float sc_cur = __int_as_float((127 - kcur) << 23);

            float acc0, acc1;
            DUAL_DOT(sh_w[p], Ea, Eb, acc0, acc1);

            u0 = msk ? acc0 : u0 * sc_cur;
            u1 = msk ? acc1 : u1 * sc_cur;

            if (lane == 0) sh_k[p] = (__float_as_int(u0) >> 23) - 127;

            w0 = u0 * es0[(k + 1) & 3] * scn;
            w1 = u1 * es1[(k + 1) & 3] * scn;
            kcur = knext;

            if (t0 + 4 < CL) {
                const float2 sv = *(const float2*)(scp + (t0 + 4 + k) * LN);
                es0[k] = __expf(sv.x);
                es1[k] = __expf(sv.y);
                mb[k] = mp[t0 + 4 + k];
            }
        }
    }
    *K_out = K;
}

// ---- backward CL-step scan: z <- es_t ∘ (E z), t from last to first ----
// Lane owns COMPONENTS (2t, 2t+1); Ra/Rb are E ROWS (contiguous trans loads).
// No K tracking: output is normalized, scale cancels in the correction dot.
__device__ __forceinline__ void chunk_scan_bw(
    const float* __restrict__ scp, const int* __restrict__ mp,
    const unsigned long long* Ra, const unsigned long long* Rb,
    float& z0, float& z1, bool act, int lane,
    float sh_w[2][LN], int sh_k[2])
{
    int kcur = 0;
    if (lane == 0) { sh_k[0] = 0; sh_k[1] = 0; }

    float es0[4], es1[4];
    int mb[4];
#pragma unroll
    for (int q = 0; q < 4; q++) {
        const int t = CL - 1 - q;
        const float2 sv = *(const float2*)(scp + t * LN);
        es0[q] = __expf(sv.x);
        es1[q] = __expf(sv.y);
        mb[q] = mp[t];
    }

    float w0 = z0, w1 = z1;
    __syncwarp();

    for (int r0 = 0; r0 < CL; r0 += 4) {
#pragma unroll
        for (int k = 0; k < 4; k++) {
            const int r = r0 + k;
            const int p = r & 1;
            const int msk = mb[k];

            if (act) {
                unsigned long long wp;
                PACK_F32X2_(wp, w0, w1);
                *(unsigned long long*)&sh_w[p][2 * lane] = wp;
            }
            __syncwarp();

            const int knext = sh_k[p ^ 1];
            const float scn = __int_as_float((127 - knext) << 23);
            const float sc_cur = __int_as_float((127 - kcur) << 23);

            float acc0, acc1;
            DUAL_DOT(sh_w[p], Ra, Rb, acc0, acc1);

            z0 = msk ? acc0 * es0[k] : z0 * sc_cur;
            z1 = msk ? acc1 * es1[k] : z1 * sc_cur;

            if (lane == 0) sh_k[p] = (__float_as_int(z0) >> 23) - 127;

            w0 = z0 * scn;
            w1 = z1 * scn;
            kcur = knext;

            if (r0 + 4 < CL) {
                const int t2 = CL - 1 - (r0 + 4 + k);
                const float2 sv = *(const float2*)(scp + t2 * LN);
                es0[k] = __expf(sv.x);
                es1[k] = __expf(sv.y);
                mb[k] = mp[t2];
            }
        }
    }
}

__device__ __forceinline__ float sumvec(const float sh[LN])
{
    float sum = 0.f;
    const float4* v4 = (const float4*)sh;
#pragma unroll
    for (int q = 0; q < LN / 4; q++) {
        const float4 v = v4[q];
        sum += (v.x + v.y) + (v.z + v.w);
    }
    return sum;
}

__device__ __forceinline__ float warp_sum(float v)
{
    v += __shfl_xor_sync(0xffffffffu, v, 16);
    v += __shfl_xor_sync(0xffffffffu, v, 8);
    v += __shfl_xor_sync(0xffffffffu, v, 4);
    v += __shfl_xor_sync(0xffffffffu, v, 2);
    v += __shfl_xor_sync(0xffffffffu, v, 1);
    return v;
}

// grid = 1024 fwd + 960 bwd + 64 tg = 2048 single-warp CTAs, ALL independent.
// Last arrival per batch (32 CTAs) stitches; last batch combines to out.
__global__ __launch_bounds__(32) void crf_main_kernel(
    const float* __restrict__ scores,
    const void* __restrict__ gold_raw,
    const int* __restrict__ mask,
    const float* __restrict__ trans,
    float* __restrict__ out)
{
    const int bid = blockIdx.x;
    const int lane = threadIdx.x;
    const bool act = (lane < LN / 2);

    __shared__ float sh_w[2][LN];
    __shared__ int sh_k[2];

    int b;
    if (bid < BN * NC) {
        // ---- forward chunk: scan from ones ----
        b = bid >> 4;
        const int c = bid & (NC - 1);
        const int j0 = act ? 2 * lane : 0;
        const int j1 = act ? 2 * lane + 1 : 0;

        unsigned long long Ea[LN / 2], Eb[LN / 2];
#pragma unroll
        for (int q = 0; q < LN / 2; q++) {
            float lo = __expf(trans[(2 * q) * LN + j0]);
            float hi = __expf(trans[(2 * q + 1) * LN + j0]);
            PACK_F32X2_(Ea[q], lo, hi);
            lo = __expf(trans[(2 * q) * LN + j1]);
            hi = __expf(trans[(2 * q + 1) * LN + j1]);
            PACK_F32X2_(Eb[q], lo, hi);
        }

        const float* scp = scores + ((size_t)b * TN + c * CL) * LN + j0;
        const int*   mp  = mask + (size_t)b * TN + c * CL;

        float u0 = 1.0f, u1 = 1.0f;   // true init for c=0 is EXACTLY ones (trans[START,:]=0)
        int K;
        chunk_scan_fw(scp, mp, Ea, Eb, u0, u1, act, lane, sh_w, sh_k, &K);

        if (act) {
            unsigned long long up;
            PACK_F32X2_(up, u0, u1);
            *(unsigned long long*)&sh_w[0][2 * lane] = up;
        }
        __syncwarp();
        const float sum = sumvec(sh_w[0]);
        if (act) {
            float2* dp = (float2*)&g_dir[b][c][2 * lane];
            *dp = make_float2(u0 / sum, u1 / sum);
        }
        if (lane == 0)
            g_S[b][c] = (float)K * 0.6931471805599453f + logf(sum);
    } else if (bid < BN * NC + BN * (NC - 1)) {
        // ---- backward chunk (left direction), c = 1..15 ----
        const int idx = bid - BN * NC;
        b = idx / (NC - 1);
        const int c = idx % (NC - 1) + 1;
        const int i0 = act ? 2 * lane : 0;
        const int i1 = act ? 2 * lane + 1 : 0;

        unsigned long long Ra[LN / 2], Rb[LN / 2];
#pragma unroll
        for (int q = 0; q < LN / 2; q++) {
            float2 tv = *(const float2*)&trans[i0 * LN + 2 * q];
            PACK_F32X2_(Ra[q], __expf(tv.x), __expf(tv.y));
            tv = *(const float2*)&trans[i1 * LN + 2 * q];
            PACK_F32X2_(Rb[q], __expf(tv.x), __expf(tv.y));
        }

        const float* scp = scores + ((size_t)b * TN + c * CL) * LN + i0;
        const int*   mp  = mask + (size_t)b * TN + c * CL;

        float z0 = 1.0f, z1 = 1.0f;
        chunk_scan_bw(scp, mp, Ra, Rb, z0, z1, act, lane, sh_w, sh_k);

        if (act) {
            unsigned long long zp;
            PACK_F32X2_(zp, z0, z1);
            *(unsigned long long*)&sh_w[0][2 * lane] = zp;
        }
        __syncwarp();
        const float sum = sumvec(sh_w[0]);
        if (act) {
            float2* ap = (float2*)&g_a[b][c][2 * lane];
            *ap = make_float2(z0 / sum, z1 / sum);
        }
    } else {
        // ---- tg gold-path energy (one warp per batch) ----
        b = bid - (BN * NC + BN * (NC - 1));

        // gold declared int64; JAX (x64 off) materializes int32 — detect via ballot:
        // true int64 => every odd 32-bit word is 0 (labels < 48).
        const int* g32 = (const int*)gold_raw;
        const int ok = (g32[2 * lane + 1] == 0) && (g32[2 * (lane + 32) + 1] == 0);
        const int is64 = (__ballot_sync(0xffffffffu, ok) == 0xffffffffu);

        float sum = 0.f;
#pragma unroll
        for (int t = lane; t < TN; t += 32) {
            const long long li = (long long)b * TN + t;
            const int g = is64 ? g32[2 * li] : g32[li];   // little-endian low word
            const float v = scores[li * LN] + trans[g];   // crf[t+1,b,0,g]
            if (mask[li]) sum += v;
        }
        if (lane == 0) sum += trans[START_I];             // t=0 term: trans[0][START]

        sum = warp_sum(sum);
        if (lane == 0) g_tg[b] = sum;
    }

    // ---- per-batch arrival; last of 32 CTAs stitches ----
    __threadfence();
    unsigned r = 0;
    if (lane == 0) r = atomicAdd(&g_bd[b], 1u);
    r = __shfl_sync(0xffffffffu, r, 0);
    if (r == 2 * NC - 1) {
        __threadfence();
        // sum of forward magnitudes
        float s = (lane < NC) ? g_S[b][lane] : 0.f;
        s = warp_sum(s);
        // rank-1 bilinear corrections: sum_c log(d_{c-1} . a_c)
        float corr = 0.f;
        for (int c2 = 1; c2 < NC; c2++) {
            float pdot = 0.f;
            if (act) {
                const float2 d2 = *(const float2*)&g_dir[b][c2 - 1][2 * lane];
                const float2 a2 = *(const float2*)&g_a[b][c2][2 * lane];
                pdot = d2.x * a2.x + d2.y * a2.y;
            }
            pdot = warp_sum(pdot);
            corr += logf(pdot);
        }
        const float fs = s + corr + logf(g_dir[b][NC - 1][END_I]);
        const float val = fs - g_tg[b];
        if (lane == 0) {
            g_val[b] = val;
            g_bd[b] = 0u;                 // reset for next graph replay
        }
        __threadfence();
        unsigned r2 = 0;
        if (lane == 0) r2 = atomicAdd(&g_done, 1u);
        r2 = __shfl_sync(0xffffffffu, r2, 0);
        if (r2 == BN - 1) {               // last batch: deterministic final combine
            __threadfence();
            float v = g_val[lane] + g_val[lane + 32];
            v = warp_sum(v);
            if (lane == 0) {
                out[0] = v / (float)BN;
                g_done = 0u;              // reset for next graph replay
            }
        }
    }
}

extern "C" void kernel_launch(void* const* d_in, const int* in_sizes, int n_in,
                              void* d_out, int out_size)
{
    const float* scores = (const float*)d_in[0];
    const void*  gold   = (const void*)d_in[1];
    const int*   mask   = (const int*)d_in[2];
    const float* trans  = (const float*)d_in[3];
    float*       out    = (float*)d_out;

    crf_main_kernel<<<BN * NC + BN * (NC - 1) + BN, 32>>>(scores, gold, mask, trans, out);
}